// round 8
// baseline (speedup 1.0000x reference)
#include <cuda_runtime.h>

#define DIM     1024
#define NF4     256               // float4 per row
#define N_CLS   10
#define IMG     784
#define IMGF4   196
#define N_SAMP  16384
#define ROWS    4                 // rows per warp-quad
#define WARPS   8
#define TPB     256
#define GRID    304               // 2 blocks/SM on 152 SMs
#define TOTW    (GRID * WARPS)    // 2432 warps
#define NQUADS  (N_SAMP / ROWS)   // 4096
#define JIT     8                 // chunks per quad (128 d each)
#define DEPTH   2                 // per-warp cp.async stages
#define REF_F4  (N_CLS * NF4)     // 2560 float4 = 40KB
#define WSTG_F4 256               // per warp per slot: {re,im}x{4 rows}x32 f4 = 4KB
#define STG_F4  (WARPS * DEPTH * WSTG_F4)   // 4096 f4 = 64KB
#define SMEM_BYTES ((REF_F4 + STG_F4) * 16 + 96 * 4)

typedef unsigned long long u64;

// ---- packed fp32x2 helpers -------------------------------------------------
__device__ __forceinline__ void ffma2(u64& d, u64 a, u64 b) {
    asm("fma.rn.f32x2 %0, %1, %2, %0;" : "+l"(d) : "l"(a), "l"(b));
}
__device__ __forceinline__ u64 addf2(u64 a, u64 b) {
    asm("add.rn.f32x2 %0, %1, %2;" : "+l"(a) : "l"(a), "l"(b));
    return a;
}
__device__ __forceinline__ u64 packf2(float lo, float hi) {
    u64 r;
    asm("mov.b64 %0, {%1, %2};" : "=l"(r) : "f"(lo), "f"(hi));
    return r;
}

// ---- cp.async helpers ------------------------------------------------------
__device__ __forceinline__ void cp_async16(void* smem_dst, const void* gsrc) {
    unsigned saddr = (unsigned)__cvta_generic_to_shared(smem_dst);
    asm volatile("cp.async.cg.shared.global [%0], [%1], 16;"
                 :: "r"(saddr), "l"(gsrc));
}
__device__ __forceinline__ void cp_commit() {
    asm volatile("cp.async.commit_group;");
}
template <int N>
__device__ __forceinline__ void cp_wait() {
    asm volatile("cp.async.wait_group %0;" :: "n"(N));
}

// ---------------------------------------------------------------------------
// out[n][c] = (z_re[n]·ref[c])^2 + (z_im[n]·ref[c])^2
// Persistent blocks (2/SM). Each WARP owns row-quads (4 rows) with a private
// DEPTH-2 cp.async pipeline; no block barriers in the main loop.
// Accumulators packed (re,im) in f32x2 lanes: 4x ref smem reuse keeps the
// shared-memory crossbar below the HBM-roof budget.
// ---------------------------------------------------------------------------
__global__ void __launch_bounds__(TPB, 2)
swap_test_kernel(const float* __restrict__ z_re,
                 const float* __restrict__ z_im,
                 const float* __restrict__ canon,
                 float* __restrict__ out)
{
    extern __shared__ float4 smem[];
    float4* ref_s = smem;                          // [N_CLS][NF4]
    float4* zst   = smem + REF_F4;                 // [WARPS][DEPTH][256]
    float*  scr   = (float*)(zst + STG_F4);        // 80 partials + 10 inv

    const int t    = threadIdx.x;
    const int warp = t >> 5;
    const int lane = t & 31;
    const int g    = blockIdx.x * WARPS + warp;    // global warp id

    const int nq      = (g + TOTW < NQUADS) ? 2 : 1;
    const int nchunks = nq * JIT;
    size_t qrow[2];
    qrow[0] = (size_t)ROWS * g;
    qrow[1] = (size_t)ROWS * (g + TOTW);

    const float4* zr4 = (const float4*)z_re;
    const float4* zi4 = (const float4*)z_im;
    float4* mystg = zst + warp * (DEPTH * WSTG_F4);

    // ---- prologue: fill both slots with chunks 0,1 of quad 0 --------------
    {
        const size_t rb = qrow[0] * NF4;
        #pragma unroll
        for (int s = 0; s < DEPTH; ++s) {
            float4* dst = mystg + s * WSTG_F4;
            #pragma unroll
            for (int r = 0; r < ROWS; ++r) {
                cp_async16(&dst[r * 32 + lane],       zr4 + rb + r * NF4 + s * 32 + lane);
                cp_async16(&dst[128 + r * 32 + lane], zi4 + rb + r * NF4 + s * 32 + lane);
            }
            cp_commit();
        }
    }

    // ---- ref prep once per block (hidden under prologue DRAM latency) -----
    {
        float ss[N_CLS];
        #pragma unroll
        for (int c = 0; c < N_CLS; ++c) ss[c] = 0.f;
        for (int i = t; i < IMG; i += TPB) {
            #pragma unroll
            for (int c = 0; c < N_CLS; ++c) {
                const float v = canon[c * IMG + i];
                ss[c] += v * v;
            }
        }
        #pragma unroll
        for (int c = 0; c < N_CLS; ++c)
            #pragma unroll
            for (int sh = 16; sh > 0; sh >>= 1)
                ss[c] += __shfl_xor_sync(0xffffffffu, ss[c], sh);
        if (lane == 0) {
            #pragma unroll
            for (int c = 0; c < N_CLS; ++c) scr[c * WARPS + warp] = ss[c];
        }
        __syncthreads();
        if (t < N_CLS) {
            float s = 0.f;
            #pragma unroll
            for (int w = 0; w < WARPS; ++w) s += scr[t * WARPS + w];
            scr[80 + t] = rsqrtf(s);
        }
        __syncthreads();
        const float4* cg4 = (const float4*)canon;   // 3136B/class: f4-aligned
        #pragma unroll
        for (int i = 0; i < REF_F4 / TPB; ++i) {
            const int idx = i * TPB + t;
            const int c   = idx / NF4;
            const int d4  = idx % NF4;
            const float inv = scr[80 + c];
            float4 v = make_float4(0.f, 0.f, 0.f, 0.f);
            if (d4 < IMGF4) {
                const float4 u = cg4[c * IMGF4 + d4];
                v = make_float4(u.x * inv, u.y * inv, u.z * inv, u.w * inv);
            }
            ref_s[idx] = v;
        }
        __syncthreads();
    }

    // ---- main loop: per-warp pipeline over quads, no block barriers -------
    int ci = 0;
    for (int qi = 0; qi < nq; ++qi) {
        u64 acc[ROWS][N_CLS];
        #pragma unroll
        for (int r = 0; r < ROWS; ++r)
            #pragma unroll
            for (int c = 0; c < N_CLS; ++c) acc[r][c] = 0ull;

        #pragma unroll
        for (int j = 0; j < JIT; ++j, ++ci) {
            const int slot = ci & (DEPTH - 1);
            cp_wait<DEPTH - 1>();                   // chunk ci's data in smem

            const float4* s = mystg + slot * WSTG_F4;
            float4 zr[ROWS], zi[ROWS];
            #pragma unroll
            for (int r = 0; r < ROWS; ++r) {
                zr[r] = s[r * 32 + lane];
                zi[r] = s[128 + r * 32 + lane];
            }

            // refill this slot with chunk ci+DEPTH (same slot index).
            // WAR safe: global return latency >> LDS latency.
            const int pf = ci + DEPTH;
            if (pf < nchunks) {
                const size_t rb = qrow[pf >> 3] * NF4 + (pf & 7) * 32 + lane;
                float4* dst = mystg + slot * WSTG_F4;
                #pragma unroll
                for (int r = 0; r < ROWS; ++r) {
                    cp_async16(&dst[r * 32 + lane],       zr4 + rb + r * NF4);
                    cp_async16(&dst[128 + r * 32 + lane], zi4 + rb + r * NF4);
                }
            }
            cp_commit();                            // always commit (may be empty)

            // pack (zr_d, zi_d) pairs: 16 u64, reused by all 10 classes
            u64 pz[ROWS][4];
            #pragma unroll
            for (int r = 0; r < ROWS; ++r) {
                pz[r][0] = packf2(zr[r].x, zi[r].x);
                pz[r][1] = packf2(zr[r].y, zi[r].y);
                pz[r][2] = packf2(zr[r].z, zi[r].z);
                pz[r][3] = packf2(zr[r].w, zi[r].w);
            }

            const float4* rbase = ref_s + j * 32 + lane;
            #pragma unroll
            for (int c = 0; c < N_CLS; ++c) {
                const float4 f = rbase[c * NF4];
                const u64 f0 = packf2(f.x, f.x);
                const u64 f1 = packf2(f.y, f.y);
                const u64 f2 = packf2(f.z, f.z);
                const u64 f3 = packf2(f.w, f.w);
                #pragma unroll
                for (int r = 0; r < ROWS; ++r) {
                    ffma2(acc[r][c], pz[r][0], f0);
                    ffma2(acc[r][c], pz[r][1], f1);
                    ffma2(acc[r][c], pz[r][2], f2);
                    ffma2(acc[r][c], pz[r][3], f3);
                }
            }
        }

        // ---- quad epilogue: butterfly the packed (re,im) sums -------------
        #pragma unroll
        for (int sh = 16; sh > 0; sh >>= 1)
            #pragma unroll
            for (int r = 0; r < ROWS; ++r)
                #pragma unroll
                for (int c = 0; c < N_CLS; ++c)
                    acc[r][c] = addf2(acc[r][c],
                                      __shfl_xor_sync(0xffffffffu, acc[r][c], sh));

        const size_t rowbase = qrow[qi];
        #pragma unroll
        for (int c = 0; c < N_CLS; ++c) {
            if (lane == c) {
                #pragma unroll
                for (int r = 0; r < ROWS; ++r) {
                    const float re = __uint_as_float((unsigned)(acc[r][c] & 0xffffffffu));
                    const float im = __uint_as_float((unsigned)(acc[r][c] >> 32));
                    out[(rowbase + r) * N_CLS + c] = re * re + im * im;
                }
            }
        }
    }
}

// ---------------------------------------------------------------------------
extern "C" void kernel_launch(void* const* d_in, const int* in_sizes, int n_in,
                              void* d_out, int out_size) {
    const float* z_re  = (const float*)d_in[0];
    const float* z_im  = (const float*)d_in[1];
    const float* canon = (const float*)d_in[2];
    float* out = (float*)d_out;

    static bool attr_set = false;
    if (!attr_set) {
        cudaFuncSetAttribute(swap_test_kernel,
                             cudaFuncAttributeMaxDynamicSharedMemorySize,
                             SMEM_BYTES);
        attr_set = true;
    }

    swap_test_kernel<<<GRID, TPB, SMEM_BYTES>>>(z_re, z_im, canon, out);
}

// round 9
// speedup vs baseline: 1.4536x; 1.4536x over previous
#include <cuda_runtime.h>
#include <cstdint>

#define DIM      1024
#define NF4      256
#define N_CLS    10
#define IMG      784
#define IMGF4    196
#define N_SAMP   16384
#define ROWS     2
#define WARPS_B  11
#define TPB      (WARPS_B * 32)     // 352
#define GRID     152                // 1 persistent block per SM
#define TOTW     (GRID * WARPS_B)   // 1672 warps
#define NPAIRS   (N_SAMP / ROWS)    // 8192 row-pairs
#define BASE_P   (NPAIRS / TOTW)    // 4
#define REM_P    (NPAIRS - BASE_P * TOTW)  // 1504 warps take 5
#define HALF_F   512                // floats per half-row
#define CHUNKS_H 4                  // j-chunks per half (128 d each)
#define SEG_B    2048               // bytes per (row,plane) segment in a slot
#define SLOT_B   (4 * SEG_B)        // 8KB: re0,re1,im0,im1
#define REF_B    (N_CLS * DIM * 4)  // 40960
#define STG_B    (WARPS_B * 2 * SLOT_B)   // 180224
#define MBAR_OFF (REF_B + STG_B)          // 221184
#define SCR_OFF  (MBAR_OFF + WARPS_B * 2 * 8)   // 221360
#define SMEM_BYTES (SCR_OFF + 128 * 4)

typedef unsigned long long u64;

// ---- packed fp32x2 helpers (d-parity accumulators, proven in R5) ----------
__device__ __forceinline__ void ffma2(u64& d, u64 a, u64 b) {
    asm("fma.rn.f32x2 %0, %1, %2, %0;" : "+l"(d) : "l"(a), "l"(b));
}
__device__ __forceinline__ u64 addf2(u64 a, u64 b) {
    asm("add.rn.f32x2 %0, %1, %2;" : "+l"(a) : "l"(a), "l"(b));
    return a;
}
__device__ __forceinline__ float pair_sum(u64 v) {
    return __uint_as_float((unsigned)(v & 0xffffffffu)) +
           __uint_as_float((unsigned)(v >> 32));
}

// ---- TMA 1D bulk + mbarrier helpers ---------------------------------------
__device__ __forceinline__ void mbar_init(unsigned mbar, unsigned cnt) {
    asm volatile("mbarrier.init.shared.b64 [%0], %1;" :: "r"(mbar), "r"(cnt) : "memory");
}
__device__ __forceinline__ void fence_proxy_async_cta() {
    asm volatile("fence.proxy.async.shared::cta;" ::: "memory");
}
__device__ __forceinline__ void mbar_expect_tx(unsigned mbar, unsigned bytes) {
    asm volatile("mbarrier.arrive.expect_tx.shared.b64 _, [%0], %1;"
                 :: "r"(mbar), "r"(bytes) : "memory");
}
__device__ __forceinline__ void bulk_g2s(unsigned sdst, const void* gsrc,
                                         unsigned bytes, unsigned mbar) {
    asm volatile(
        "cp.async.bulk.shared::cta.global.mbarrier::complete_tx::bytes "
        "[%0], [%1], %2, [%3];"
        :: "r"(sdst), "l"(gsrc), "r"(bytes), "r"(mbar) : "memory");
}
__device__ __forceinline__ void mbar_wait(unsigned mbar, unsigned phase) {
    unsigned done = 0;
    while (!done) {
        asm volatile(
            "{\n\t.reg .pred p;\n\t"
            "mbarrier.try_wait.parity.shared.b64 p, [%1], %2;\n\t"
            "selp.u32 %0, 1, 0, p;\n\t}"
            : "=r"(done) : "r"(mbar), "r"(phase));
    }
}

// ---------------------------------------------------------------------------
// out[n][c] = (z_re[n]·ref[c])^2 + (z_im[n]·ref[c])^2
// One persistent 352-thread block per SM. Each warp owns row-pairs; z is
// staged into smem by the TMA engine (cp.async.bulk, 2KB contiguous ops)
// through a private 2-slot ring with mbarrier expect_tx — no LDGSTS, no
// block barriers in the main loop. Compute = R5's d-parity packed FFMA2.
// ---------------------------------------------------------------------------
__global__ void __launch_bounds__(TPB, 1)
swap_test_kernel(const float* __restrict__ z_re,
                 const float* __restrict__ z_im,
                 const float* __restrict__ canon,
                 float* __restrict__ out)
{
    extern __shared__ char smem_raw[];
    float4* ref_s = (float4*)smem_raw;                 // 40KB
    char*   stg   = smem_raw + REF_B;                  // [WARPS_B][2][8KB]
    float*  scr   = (float*)(smem_raw + SCR_OFF);

    const int t    = threadIdx.x;
    const int warp = t >> 5;
    const int lane = t & 31;

    const unsigned smem_base = (unsigned)__cvta_generic_to_shared(smem_raw);
    const unsigned my_slot0  = smem_base + REF_B + warp * (2 * SLOT_B);
    const unsigned my_mbar0  = smem_base + MBAR_OFF + warp * 16;

    // balanced warp -> row-pair mapping (spreads the +1 pairs across blocks)
    const int gg = warp * GRID + blockIdx.x;
    const int np = BASE_P + (gg < REM_P ? 1 : 0);
    const int nstages = 2 * np;                        // half-row stages

    // ---- per-warp TMA ring init + prologue (stages 0,1 = pair0) -----------
    if (lane == 0) {
        mbar_init(my_mbar0, 1);
        mbar_init(my_mbar0 + 8, 1);
        fence_proxy_async_cta();
        const size_t row0 = (size_t)ROWS * gg;
        #pragma unroll
        for (int s = 0; s < 2; ++s) {                  // s = half index (h)
            const unsigned slot = my_slot0 + s * SLOT_B;
            const unsigned mb   = my_mbar0 + s * 8;
            mbar_expect_tx(mb, SLOT_B);
            const size_t off = (row0 * DIM + (size_t)s * HALF_F) * 4;
            bulk_g2s(slot,             (const char*)z_re + off,             SEG_B, mb);
            bulk_g2s(slot + SEG_B,     (const char*)z_re + off + DIM * 4,   SEG_B, mb);
            bulk_g2s(slot + 2 * SEG_B, (const char*)z_im + off,             SEG_B, mb);
            bulk_g2s(slot + 3 * SEG_B, (const char*)z_im + off + DIM * 4,   SEG_B, mb);
        }
    }

    // ---- ref prep once per block (overlapped with TMA prologue) -----------
    {
        float ss[N_CLS];
        #pragma unroll
        for (int c = 0; c < N_CLS; ++c) ss[c] = 0.f;
        for (int i = t; i < IMG; i += TPB) {
            #pragma unroll
            for (int c = 0; c < N_CLS; ++c) {
                const float v = canon[c * IMG + i];
                ss[c] += v * v;
            }
        }
        #pragma unroll
        for (int c = 0; c < N_CLS; ++c)
            #pragma unroll
            for (int sh = 16; sh > 0; sh >>= 1)
                ss[c] += __shfl_xor_sync(0xffffffffu, ss[c], sh);
        if (lane == 0) {
            #pragma unroll
            for (int c = 0; c < N_CLS; ++c) scr[c * WARPS_B + warp] = ss[c];
        }
        __syncthreads();
        if (t < N_CLS) {
            float s = 0.f;
            #pragma unroll
            for (int w = 0; w < WARPS_B; ++w) s += scr[t * WARPS_B + w];
            scr[112 + t] = rsqrtf(s);
        }
        __syncthreads();
        const float4* cg4 = (const float4*)canon;      // 3136B/class, aligned
        for (int idx = t; idx < N_CLS * NF4; idx += TPB) {
            const int c  = idx / NF4;
            const int d4 = idx % NF4;
            const float inv = scr[112 + c];
            float4 v = make_float4(0.f, 0.f, 0.f, 0.f);
            if (d4 < IMGF4) {
                const float4 u = cg4[c * IMGF4 + d4];
                v = make_float4(u.x * inv, u.y * inv, u.z * inv, u.w * inv);
            }
            ref_s[idx] = v;
        }
        __syncthreads();
    }

    // ---- main loop: per-warp TMA ring, no block barriers ------------------
    u64 accR[ROWS][N_CLS], accI[ROWS][N_CLS];
    #pragma unroll
    for (int r = 0; r < ROWS; ++r)
        #pragma unroll
        for (int c = 0; c < N_CLS; ++c) { accR[r][c] = 0ull; accI[r][c] = 0ull; }

    int s = 0;                                         // global stage counter
    for (int k = 0; k < np; ++k) {
        const size_t pair = (size_t)gg + (size_t)k * TOTW;

        #pragma unroll
        for (int h = 0; h < 2; ++h, ++s) {
            const int      sl   = s & 1;
            const unsigned mb   = my_mbar0 + sl * 8;
            const unsigned slot = my_slot0 + sl * SLOT_B;
            mbar_wait(mb, (s >> 1) & 1);               // stage s data resident

            #pragma unroll
            for (int j = 0; j < CHUNKS_H; ++j) {
                const unsigned zoff = slot + j * 512 + lane * 16;
                ulonglong2 zr0, zr1, zi0, zi1;
                asm volatile("ld.shared.v2.u64 {%0,%1}, [%2];"
                             : "=l"(zr0.x), "=l"(zr0.y) : "r"(zoff));
                asm volatile("ld.shared.v2.u64 {%0,%1}, [%2];"
                             : "=l"(zr1.x), "=l"(zr1.y) : "r"(zoff + SEG_B));
                asm volatile("ld.shared.v2.u64 {%0,%1}, [%2];"
                             : "=l"(zi0.x), "=l"(zi0.y) : "r"(zoff + 2 * SEG_B));
                asm volatile("ld.shared.v2.u64 {%0,%1}, [%2];"
                             : "=l"(zi1.x), "=l"(zi1.y) : "r"(zoff + 3 * SEG_B));

                const int jg = h * CHUNKS_H + j;       // global chunk 0..7
                const float4* rbase = ref_s + jg * 32 + lane;
                #pragma unroll
                for (int c = 0; c < N_CLS; ++c) {
                    const ulonglong2 f2 = *(const ulonglong2*)&rbase[c * NF4];
                    ffma2(accR[0][c], zr0.x, f2.x);
                    ffma2(accR[0][c], zr0.y, f2.y);
                    ffma2(accR[1][c], zr1.x, f2.x);
                    ffma2(accR[1][c], zr1.y, f2.y);
                    ffma2(accI[0][c], zi0.x, f2.x);
                    ffma2(accI[0][c], zi0.y, f2.y);
                    ffma2(accI[1][c], zi1.x, f2.x);
                    ffma2(accI[1][c], zi1.y, f2.y);
                }
            }

            __syncwarp();                              // all lanes done with slot
            // refill this slot with stage s+2 (same slot index)
            if (lane == 0 && s + 2 < nstages) {
                const int    s2    = s + 2;
                const size_t pair2 = (size_t)gg + (size_t)(s2 >> 1) * TOTW;
                const size_t row2  = (size_t)ROWS * pair2;
                const int    h2    = s2 & 1;
                mbar_expect_tx(mb, SLOT_B);
                const size_t off = (row2 * DIM + (size_t)h2 * HALF_F) * 4;
                bulk_g2s(slot,             (const char*)z_re + off,           SEG_B, mb);
                bulk_g2s(slot + SEG_B,     (const char*)z_re + off + DIM * 4, SEG_B, mb);
                bulk_g2s(slot + 2 * SEG_B, (const char*)z_im + off,           SEG_B, mb);
                bulk_g2s(slot + 3 * SEG_B, (const char*)z_im + off + DIM * 4, SEG_B, mb);
            }
        }

        // ---- pair epilogue: butterfly-reduce, square, write ---------------
        u64 pk[ROWS][N_CLS];
        #pragma unroll
        for (int r = 0; r < ROWS; ++r)
            #pragma unroll
            for (int c = 0; c < N_CLS; ++c) {
                u64 p;
                asm("mov.b64 %0, {%1, %2};" : "=l"(p)
                    : "f"(pair_sum(accR[r][c])), "f"(pair_sum(accI[r][c])));
                pk[r][c] = p;
                accR[r][c] = 0ull; accI[r][c] = 0ull;
            }
        #pragma unroll
        for (int sh = 16; sh > 0; sh >>= 1)
            #pragma unroll
            for (int r = 0; r < ROWS; ++r)
                #pragma unroll
                for (int c = 0; c < N_CLS; ++c)
                    pk[r][c] = addf2(pk[r][c],
                                     __shfl_xor_sync(0xffffffffu, pk[r][c], sh));

        const size_t rowbase = (size_t)ROWS * pair;
        #pragma unroll
        for (int c = 0; c < N_CLS; ++c) {
            if (lane == c) {
                #pragma unroll
                for (int r = 0; r < ROWS; ++r) {
                    const float re = __uint_as_float((unsigned)(pk[r][c] & 0xffffffffu));
                    const float im = __uint_as_float((unsigned)(pk[r][c] >> 32));
                    out[(rowbase + r) * N_CLS + c] = re * re + im * im;
                }
            }
        }
    }
}

// ---------------------------------------------------------------------------
extern "C" void kernel_launch(void* const* d_in, const int* in_sizes, int n_in,
                              void* d_out, int out_size) {
    const float* z_re  = (const float*)d_in[0];
    const float* z_im  = (const float*)d_in[1];
    const float* canon = (const float*)d_in[2];
    float* out = (float*)d_out;

    static bool attr_set = false;
    if (!attr_set) {
        cudaFuncSetAttribute(swap_test_kernel,
                             cudaFuncAttributeMaxDynamicSharedMemorySize,
                             SMEM_BYTES);
        attr_set = true;
    }

    swap_test_kernel<<<GRID, TPB, SMEM_BYTES>>>(z_re, z_im, canon, out);
}